// round 9
// baseline (speedup 1.0000x reference)
#include <cuda_runtime.h>
#include <cuda_bf16.h>
#include <math.h>
#include <stdint.h>

#define NN 100000
#define NE 1600000
#define DD 128
#define CC 64
#define NL 4

// ---------------- scratch (device globals: allocation-free) ----------------
__device__ float g_h0[NN * DD];
__device__ float g_hA[NN * DD];
__device__ float g_hB[NN * DD];
__device__ float g_sup[NN * DD];
__device__ int   g_rowptr[NN + 1];
__device__ int   g_cursor[NN];
__device__ int   g_col[NE];
__device__ float g_val[NE];
__device__ int   g_bsum[128];

// ---------------- warp-MMA helpers (sm_80-class PTX: no arch suffix needed) ----
__device__ __forceinline__ uint32_t smem_u32(const void* p) {
    uint32_t a;
    asm("{ .reg .u64 t; cvta.to.shared.u64 t, %1; cvt.u32.u64 %0, t; }" : "=r"(a) : "l"(p));
    return a;
}
__device__ __forceinline__ void ldm_x4(uint32_t& a0, uint32_t& a1, uint32_t& a2, uint32_t& a3,
                                       uint32_t addr) {
    asm volatile("ldmatrix.sync.aligned.m8n8.x4.shared.b16 {%0,%1,%2,%3}, [%4];"
                 : "=r"(a0), "=r"(a1), "=r"(a2), "=r"(a3) : "r"(addr));
}
__device__ __forceinline__ void ldm_x2t(uint32_t& b0, uint32_t& b1, uint32_t addr) {
    asm volatile("ldmatrix.sync.aligned.m8n8.x2.trans.shared.b16 {%0,%1}, [%2];"
                 : "=r"(b0), "=r"(b1) : "r"(addr));
}
__device__ __forceinline__ void mma_bf16(float* c, uint32_t a0, uint32_t a1, uint32_t a2,
                                         uint32_t a3, uint32_t b0, uint32_t b1) {
    asm volatile(
        "mma.sync.aligned.m16n8k16.row.col.f32.bf16.bf16.f32 "
        "{%0,%1,%2,%3}, {%4,%5,%6,%7}, {%8,%9}, {%0,%1,%2,%3};"
        : "+f"(c[0]), "+f"(c[1]), "+f"(c[2]), "+f"(c[3])
        : "r"(a0), "r"(a1), "r"(a2), "r"(a3), "r"(b0), "r"(b1));
}
__device__ __forceinline__ void split_bf16(float v, __nv_bfloat16& h, __nv_bfloat16& l) {
    h = __float2bfloat16(v);
    l = __float2bfloat16(v - __bfloat162float(h));
}

// ---------------- CSR build ----------------
__global__ void k_zero_rowptr() {
    int i = blockIdx.x * blockDim.x + threadIdx.x;
    if (i <= NN) g_rowptr[i] = 0;
}
__global__ void k_hist(const int* __restrict__ edst) {
    int i = blockIdx.x * blockDim.x + threadIdx.x;
    if (i < NE) atomicAdd(&g_rowptr[edst[i] + 1], 1);
}
__global__ void k_scan1() {
    __shared__ int sh[2][1024];
    int t = threadIdx.x;
    int i = blockIdx.x * 1024 + t;
    int v = (i <= NN) ? g_rowptr[i] : 0;
    sh[0][t] = v;
    __syncthreads();
    int p = 0;
    #pragma unroll
    for (int off = 1; off < 1024; off <<= 1) {
        int q = p ^ 1;
        int add = (t >= off) ? sh[p][t - off] : 0;
        sh[q][t] = sh[p][t] + add;
        __syncthreads();
        p = q;
    }
    if (i <= NN) g_rowptr[i] = sh[p][t];
    if (t == 1023) g_bsum[blockIdx.x] = sh[p][1023];
}
__global__ void k_scan2(int nb) {
    __shared__ int sh[128];
    int t = threadIdx.x;
    if (t < nb) sh[t] = g_bsum[t];
    __syncthreads();
    if (t == 0) {
        int s = 0;
        for (int b = 0; b < nb; b++) { s += sh[b]; sh[b] = s; }
    }
    __syncthreads();
    if (t < nb) g_bsum[t] = sh[t];
}
__global__ void k_scan3() {
    int t = threadIdx.x;
    int i = blockIdx.x * 1024 + t;
    if (i <= NN) {
        int v = g_rowptr[i];
        if (blockIdx.x > 0) v += g_bsum[blockIdx.x - 1];
        g_rowptr[i] = v;
        if (i < NN) g_cursor[i] = v;
    }
}
__global__ void k_fill(const int* __restrict__ esrc, const int* __restrict__ edst,
                       const float* __restrict__ ew) {
    int i = blockIdx.x * blockDim.x + threadIdx.x;
    if (i < NE) {
        int d = edst[i];
        int p = atomicAdd(&g_cursor[d], 1);
        g_col[p] = esrc[i];
        g_val[p] = ew[i];
    }
}

// ---------------- SpMM: g_sup = 0.9*A@hin + 0.1*h0, warp-per-row ----------------
__global__ void k_spmm(const float* __restrict__ hin) {
    int gw = (blockIdx.x * blockDim.x + threadIdx.x) >> 5;
    int lane = threadIdx.x & 31;
    if (gw >= NN) return;
    int s = g_rowptr[gw], e = g_rowptr[gw + 1];
    const float4* h4 = (const float4*)hin;
    float4 acc = make_float4(0.f, 0.f, 0.f, 0.f);
    for (int i = s; i < e; i++) {
        int c = __ldg(&g_col[i]);
        float w = __ldg(&g_val[i]);
        float4 v = h4[c * 32 + lane];
        acc.x += w * v.x; acc.y += w * v.y; acc.z += w * v.z; acc.w += w * v.w;
    }
    const float4* h04 = (const float4*)g_h0;
    float4 z = h04[gw * 32 + lane];
    float4 r;
    r.x = 0.9f * acc.x + 0.1f * z.x;
    r.y = 0.9f * acc.y + 0.1f * z.y;
    r.z = 0.9f * acc.z + 0.1f * z.z;
    r.w = 0.9f * acc.w + 0.1f * z.w;
    ((float4*)g_sup)[gw * 32 + lane] = r;
}

// ---------------- MMA GEMM: out = relu(c0*(A@W) + c1*A + hprev + bias) ----------------
// bf16x3 split-precision via mma.sync m16n8k16. Block tile 128x128, K=128.
// 8 warps: mw = w&3 (M group of 32), nw = w>>2 (N group of 64). Warp tile 32x64.
// SMEM (bf16, padded rows of 136): Ahi | Alo : [m][k]; Bhi | Blo : [k][n].
#define PADK 136
#define TILE_B (128 * PADK * 2)          // 34816 bytes per tile
#define OFF_AHI 0
#define OFF_ALO (TILE_B)
#define OFF_BHI (2 * TILE_B)
#define OFF_BLO (3 * TILE_B)
#define MMA_SMEM (4 * TILE_B)            // 139264

__global__ void __launch_bounds__(256) k_gemm_mma(
    const float* __restrict__ A, const float* __restrict__ W,
    const float* __restrict__ hprev, const float* __restrict__ bias,
    float* __restrict__ out, float c0, float c1)
{
    extern __shared__ char sm[];
    uint32_t sb = smem_u32(sm);
    int t = threadIdx.x, lane = t & 31, warp = t >> 5;
    int mw = warp & 3, nw = warp >> 2;
    int base = blockIdx.x * 128;

    __nv_bfloat162* Ahi = (__nv_bfloat162*)(sm + OFF_AHI);
    __nv_bfloat162* Alo = (__nv_bfloat162*)(sm + OFF_ALO);
    __nv_bfloat162* Bhi = (__nv_bfloat162*)(sm + OFF_BHI);
    __nv_bfloat162* Blo = (__nv_bfloat162*)(sm + OFF_BLO);

    // A tile: [m][k], rows of 136 bf16 (indexing in bf16x2 units: row*68 + k/2)
    const float4* A4 = (const float4*)(A + (size_t)base * DD);
    #pragma unroll 2
    for (int i = 0; i < 16; i++) {
        int f = t + i * 256;               // 0..4095
        int row = f >> 5, c4 = f & 31, grow = base + row;
        float4 s = make_float4(0.f, 0.f, 0.f, 0.f);
        if (grow < NN) s = A4[f];
        __nv_bfloat16 hx, lx, hy, ly, hz, lz, hw, lw;
        split_bf16(s.x, hx, lx); split_bf16(s.y, hy, ly);
        split_bf16(s.z, hz, lz); split_bf16(s.w, hw, lw);
        int idx = row * 68 + c4 * 2;
        Ahi[idx]     = __nv_bfloat162(hx, hy);
        Ahi[idx + 1] = __nv_bfloat162(hz, hw);
        Alo[idx]     = __nv_bfloat162(lx, ly);
        Alo[idx + 1] = __nv_bfloat162(lz, lw);
    }
    // B tile: W[k][n] natural layout, rows of 136 bf16
    const float4* W4 = (const float4*)W;
    #pragma unroll 2
    for (int i = 0; i < 16; i++) {
        int f = t + i * 256;
        int k = f >> 5, c4 = f & 31;
        float4 s = W4[f];
        __nv_bfloat16 hx, lx, hy, ly, hz, lz, hw, lw;
        split_bf16(s.x, hx, lx); split_bf16(s.y, hy, ly);
        split_bf16(s.z, hz, lz); split_bf16(s.w, hw, lw);
        int idx = k * 68 + c4 * 2;
        Bhi[idx]     = __nv_bfloat162(hx, hy);
        Bhi[idx + 1] = __nv_bfloat162(hz, hw);
        Blo[idx]     = __nv_bfloat162(lx, ly);
        Blo[idx + 1] = __nv_bfloat162(lz, lw);
    }
    __syncthreads();

    float acc[2][8][4];
    #pragma unroll
    for (int mt = 0; mt < 2; mt++)
        #pragma unroll
        for (int nt = 0; nt < 8; nt++)
            #pragma unroll
            for (int j = 0; j < 4; j++) acc[mt][nt][j] = 0.f;

    // ldmatrix addressing:
    // A x4: lanes 0-15 -> row (m0 + l), k0 ; lanes 16-31 -> row (m0 + l-16), k0+8
    int arow = mw * 32 + (lane & 15);
    int akoff = (lane >> 4) * 8;
    // B x2.trans: lanes 0-15 -> row (k0 + l), n0
    int bk = lane & 15;

    const uint32_t offA[3] = { OFF_AHI, OFF_AHI, OFF_ALO };
    const uint32_t offB[3] = { OFF_BHI, OFF_BLO, OFF_BHI };

    #pragma unroll
    for (int p = 0; p < 3; p++) {
        uint32_t aB = sb + offA[p];
        uint32_t bB = sb + offB[p];
        #pragma unroll
        for (int ks = 0; ks < 8; ks++) {
            int k0 = ks * 16;
            uint32_t af[2][4];
            #pragma unroll
            for (int mt = 0; mt < 2; mt++) {
                uint32_t addr = aB + (uint32_t)(((arow + mt * 16) * PADK + k0 + akoff) * 2);
                ldm_x4(af[mt][0], af[mt][1], af[mt][2], af[mt][3], addr);
            }
            uint32_t bf[8][2];
            #pragma unroll
            for (int nt = 0; nt < 8; nt++) {
                uint32_t addr = bB + (uint32_t)(((k0 + bk) * PADK + nw * 64 + nt * 8) * 2);
                ldm_x2t(bf[nt][0], bf[nt][1], addr);
            }
            #pragma unroll
            for (int mt = 0; mt < 2; mt++)
                #pragma unroll
                for (int nt = 0; nt < 8; nt++)
                    mma_bf16(acc[mt][nt], af[mt][0], af[mt][1], af[mt][2], af[mt][3],
                             bf[nt][0], bf[nt][1]);
        }
    }

    // epilogue: fragment (row,col) mapping: c0,c1 @ (r + l/4, c + 2*(l%4)), c2,c3 @ r+8
    int rbase = base + mw * 32 + (lane >> 2);
    int cbase = nw * 64 + 2 * (lane & 3);
    #pragma unroll
    for (int mt = 0; mt < 2; mt++) {
        #pragma unroll
        for (int half = 0; half < 2; half++) {
            int grow = rbase + mt * 16 + half * 8;
            if (grow >= NN) continue;
            const float* arow_p = A + (size_t)grow * DD;
            const float* hrow_p = hprev ? hprev + (size_t)grow * DD : (const float*)0;
            float* orow_p = out + (size_t)grow * DD;
            #pragma unroll
            for (int nt = 0; nt < 8; nt++) {
                int gc = cbase + nt * 8;
                float2 av = *(const float2*)(arow_p + gc);
                float vx = acc[mt][nt][half * 2 + 0];
                float vy = acc[mt][nt][half * 2 + 1];
                float ox = c0 * vx + c1 * av.x;
                float oy = c0 * vy + c1 * av.y;
                if (hrow_p) {
                    float2 hv = *(const float2*)(hrow_p + gc);
                    ox += hv.x; oy += hv.y;
                }
                if (bias) {
                    float2 bv = *(const float2*)(bias + gc);
                    ox += bv.x; oy += bv.y;
                }
                *(float2*)(orow_p + gc) = make_float2(fmaxf(ox, 0.f), fmaxf(oy, 0.f));
            }
        }
    }
}

// ---------------- output head: logits = h@w_out + b_out -> log_softmax ----------------
__global__ void k_out(const float* __restrict__ hin, const float* __restrict__ wout,
                      const float* __restrict__ bout, float* __restrict__ out)
{
    __shared__ float Wsh[DD * CC];   // 32KB
    __shared__ float Hsh[8][DD];     // 4KB
    int t = threadIdx.x;

    float4* Wsh4 = (float4*)Wsh;
    const float4* w4 = (const float4*)wout;
    #pragma unroll
    for (int i = 0; i < 8; i++) Wsh4[t + i * 256] = w4[t + i * 256];
    __syncthreads();

    int warp = t >> 5, lane = t & 31;
    int row = blockIdx.x * 8 + warp;
    if (row >= NN) return;

    ((float4*)Hsh[warp])[lane] = ((const float4*)hin)[row * 32 + lane];
    __syncwarp();

    float a0 = bout[2 * lane], a1 = bout[2 * lane + 1];
    const float2* Wsh2 = (const float2*)Wsh;
    #pragma unroll 4
    for (int k = 0; k < DD; k++) {
        float hv = Hsh[warp][k];
        float2 w = Wsh2[k * 32 + lane];
        a0 += hv * w.x;
        a1 += hv * w.y;
    }

    float m = fmaxf(a0, a1);
    #pragma unroll
    for (int off = 16; off; off >>= 1) m = fmaxf(m, __shfl_xor_sync(0xffffffffu, m, off));
    float se = expf(a0 - m) + expf(a1 - m);
    #pragma unroll
    for (int off = 16; off; off >>= 1) se += __shfl_xor_sync(0xffffffffu, se, off);
    float lse = m + logf(se);

    out[row * 64 + 2 * lane]     = a0 - lse;
    out[row * 64 + 2 * lane + 1] = a1 - lse;
}

// ---------------- launch ----------------
extern "C" void kernel_launch(void* const* d_in, const int* in_sizes, int n_in,
                              void* d_out, int out_size)
{
    const float* x     = (const float*)d_in[0];
    const int*   esrc  = (const int*)  d_in[1];
    const int*   edst  = (const int*)  d_in[2];
    const float* ew    = (const float*)d_in[3];
    const float* w_in  = (const float*)d_in[4];
    const float* b_in  = (const float*)d_in[5];
    const float* gcn_w = (const float*)d_in[6];
    const float* w_out = (const float*)d_in[7];
    const float* b_out = (const float*)d_in[8];
    float* out = (float*)d_out;

    cudaFuncSetAttribute(k_gemm_mma, cudaFuncAttributeMaxDynamicSharedMemorySize, MMA_SMEM);

    void *ph0v, *phAv, *phBv, *psupv;
    cudaGetSymbolAddress(&ph0v, g_h0);
    cudaGetSymbolAddress(&phAv, g_hA);
    cudaGetSymbolAddress(&phBv, g_hB);
    cudaGetSymbolAddress(&psupv, g_sup);
    float* ph0 = (float*)ph0v;
    float* phA = (float*)phAv;
    float* phB = (float*)phBv;
    float* psup = (float*)psupv;

    const int NB = (NN + 1 + 1023) / 1024; // 98

    // CSR build
    k_zero_rowptr<<<(NN + 1 + 255) / 256, 256>>>();
    k_hist<<<(NE + 255) / 256, 256>>>(edst);
    k_scan1<<<NB, 1024>>>();
    k_scan2<<<1, 128>>>(NB);
    k_scan3<<<NB, 1024>>>();
    k_fill<<<(NE + 255) / 256, 256>>>(esrc, edst, ew);

    const int GB = (NN + 127) / 128;  // 782 MMA blocks
    const int SB = NN / 8;            // 12500 warp-per-row blocks

    // h0 = relu(x @ w_in + b_in)
    k_gemm_mma<<<GB, 256, MMA_SMEM>>>(x, w_in, nullptr, b_in, ph0, 1.0f, 0.0f);

    float theta[NL];
    for (int l = 0; l < NL; l++) theta[l] = logf(0.5f / (float)(l + 2) + 1.0f);

    for (int l = 0; l < NL; l++) {
        float* hin  = (l == 0) ? ph0 : ((l & 1) ? phA : phB);
        float* hout = (l & 1) ? phB : phA;
        k_spmm<<<SB, 256>>>(hin);  // g_sup = 0.9*A@hin + 0.1*h0
        // hout = relu(theta*(sup@W) + (1-theta)*sup + hin)
        k_gemm_mma<<<GB, 256, MMA_SMEM>>>(psup, gcn_w + l * DD * DD, hin, nullptr,
                                          hout, theta[l], 1.0f - theta[l]);
    }

    // final h in g_hB
    k_out<<<SB, 256>>>(phB, w_out, b_out, out);
}

// round 11
// speedup vs baseline: 1.0231x; 1.0231x over previous
#include <cuda_runtime.h>
#include <cuda_bf16.h>
#include <math.h>
#include <stdint.h>

#define NN 100000
#define NE 1600000
#define DD 128
#define CC 64
#define NL 4

// ---------------- scratch (device globals: allocation-free) ----------------
__device__ float g_h0[NN * DD];
__device__ float g_hA[NN * DD];
__device__ float g_hB[NN * DD];
__device__ float g_sup[NN * DD];
__device__ int   g_rowptr[NN + 1];
__device__ int   g_cursor[NN];
__device__ int   g_col[NE];
__device__ float g_val[NE];
__device__ int   g_bsum[128];

// ---------------- packed f32x2 helpers (sm_100-family PTX, no 'a' suffix) ----
__device__ __forceinline__ uint64_t bcast2(float v) {
    uint64_t r;
    asm("mov.b64 %0, {%1, %1};" : "=l"(r) : "f"(v));
    return r;
}
__device__ __forceinline__ uint64_t fma2(uint64_t a, uint64_t b, uint64_t c) {
    uint64_t d;
    asm("fma.rn.f32x2 %0, %1, %2, %3;" : "=l"(d) : "l"(a), "l"(b), "l"(c));
    return d;
}
__device__ __forceinline__ float2 unpack2(uint64_t v) {
    float2 f;
    asm("mov.b64 {%0, %1}, %2;" : "=f"(f.x), "=f"(f.y) : "l"(v));
    return f;
}

// ---------------- CSR build ----------------
__global__ void k_zero_rowptr() {
    int i = blockIdx.x * blockDim.x + threadIdx.x;
    if (i <= NN) g_rowptr[i] = 0;
}
__global__ void k_hist(const int* __restrict__ edst) {
    int i = blockIdx.x * blockDim.x + threadIdx.x;
    if (i < NE) atomicAdd(&g_rowptr[edst[i] + 1], 1);
}
__global__ void k_scan1() {
    __shared__ int sh[2][1024];
    int t = threadIdx.x;
    int i = blockIdx.x * 1024 + t;
    int v = (i <= NN) ? g_rowptr[i] : 0;
    sh[0][t] = v;
    __syncthreads();
    int p = 0;
    #pragma unroll
    for (int off = 1; off < 1024; off <<= 1) {
        int q = p ^ 1;
        int add = (t >= off) ? sh[p][t - off] : 0;
        sh[q][t] = sh[p][t] + add;
        __syncthreads();
        p = q;
    }
    if (i <= NN) g_rowptr[i] = sh[p][t];
    if (t == 1023) g_bsum[blockIdx.x] = sh[p][1023];
}
__global__ void k_scan2(int nb) {
    __shared__ int sh[128];
    int t = threadIdx.x;
    if (t < nb) sh[t] = g_bsum[t];
    __syncthreads();
    if (t == 0) {
        int s = 0;
        for (int b = 0; b < nb; b++) { s += sh[b]; sh[b] = s; }
    }
    __syncthreads();
    if (t < nb) g_bsum[t] = sh[t];
}
__global__ void k_scan3() {
    int t = threadIdx.x;
    int i = blockIdx.x * 1024 + t;
    if (i <= NN) {
        int v = g_rowptr[i];
        if (blockIdx.x > 0) v += g_bsum[blockIdx.x - 1];
        g_rowptr[i] = v;
        if (i < NN) g_cursor[i] = v;
    }
}
__global__ void k_fill(const int* __restrict__ esrc, const int* __restrict__ edst,
                       const float* __restrict__ ew) {
    int i = blockIdx.x * blockDim.x + threadIdx.x;
    if (i < NE) {
        int d = edst[i];
        int p = atomicAdd(&g_cursor[d], 1);
        g_col[p] = esrc[i];
        g_val[p] = ew[i];
    }
}

// ---------------- SpMM: g_sup = 0.9*A@hin + 0.1*h0, warp-per-row, 2-way MLP ----
__global__ void k_spmm(const float* __restrict__ hin) {
    int gw = (blockIdx.x * blockDim.x + threadIdx.x) >> 5;
    int lane = threadIdx.x & 31;
    if (gw >= NN) return;
    int s = g_rowptr[gw], e = g_rowptr[gw + 1];
    const float4* h4 = (const float4*)hin;
    float4 acc0 = make_float4(0.f, 0.f, 0.f, 0.f);
    float4 acc1 = make_float4(0.f, 0.f, 0.f, 0.f);
    int i = s;
    for (; i + 2 <= e; i += 2) {
        int c0 = __ldg(&g_col[i]);
        int c1 = __ldg(&g_col[i + 1]);
        float w0 = __ldg(&g_val[i]);
        float w1 = __ldg(&g_val[i + 1]);
        float4 v0 = h4[c0 * 32 + lane];
        float4 v1 = h4[c1 * 32 + lane];
        acc0.x += w0 * v0.x; acc0.y += w0 * v0.y; acc0.z += w0 * v0.z; acc0.w += w0 * v0.w;
        acc1.x += w1 * v1.x; acc1.y += w1 * v1.y; acc1.z += w1 * v1.z; acc1.w += w1 * v1.w;
    }
    if (i < e) {
        int c = __ldg(&g_col[i]);
        float w = __ldg(&g_val[i]);
        float4 v = h4[c * 32 + lane];
        acc0.x += w * v.x; acc0.y += w * v.y; acc0.z += w * v.z; acc0.w += w * v.w;
    }
    acc0.x += acc1.x; acc0.y += acc1.y; acc0.z += acc1.z; acc0.w += acc1.w;
    const float4* h04 = (const float4*)g_h0;
    float4 z = h04[gw * 32 + lane];
    float4 r;
    r.x = 0.9f * acc0.x + 0.1f * z.x;
    r.y = 0.9f * acc0.y + 0.1f * z.y;
    r.z = 0.9f * acc0.z + 0.1f * z.z;
    r.w = 0.9f * acc0.w + 0.1f * z.w;
    ((float4*)g_sup)[gw * 32 + lane] = r;
}

// ---------------- GEMM: out = relu(c0*(A@W) + c1*A + hprev + bias) ----------------
// f32x2 packed-FMA SIMT GEMM. W [128,128] in shared (64KB), S tile 64 rows (32KB).
// 8 warps, 8 rows/warp, lane owns 4 output cols (as 2 packed f32x2 accumulators/row).
__global__ void __launch_bounds__(256, 2) k_gemm(
    const float* __restrict__ A, const float* __restrict__ W,
    const float* __restrict__ hprev, const float* __restrict__ bias,
    float* __restrict__ out, float c0, float c1)
{
    extern __shared__ float sh[];
    float* Wsh = sh;                 // 128*128
    float* Ssh = sh + DD * DD;       // 64*128
    int t = threadIdx.x;

    float4* Wsh4 = (float4*)Wsh;
    const float4* W4 = (const float4*)W;
    #pragma unroll
    for (int i = 0; i < 16; i++) Wsh4[t + i * 256] = W4[t + i * 256];

    int base = blockIdx.x * 64;
    float4* Ssh4 = (float4*)Ssh;
    const float4* A4 = (const float4*)A;
    #pragma unroll
    for (int i = 0; i < 8; i++) {
        int f = t + i * 256;           // float4 index in tile, 0..2047
        int row = base + (f >> 5);
        Ssh4[f] = (row < NN) ? A4[base * 32 + f] : make_float4(0.f, 0.f, 0.f, 0.f);
    }
    __syncthreads();

    int warp = t >> 5, lane = t & 31;
    int srow = warp * 8;

    uint64_t acc[8][2];
    #pragma unroll
    for (int r = 0; r < 8; r++) { acc[r][0] = 0ull; acc[r][1] = 0ull; }

    const ulonglong2* Wshp = (const ulonglong2*)Wsh;   // same indexing as float4
    #pragma unroll 4
    for (int k = 0; k < DD; k += 2) {
        ulonglong2 wa = Wshp[k * 32 + lane];           // cols (4) at depth k
        ulonglong2 wb = Wshp[(k + 1) * 32 + lane];     // cols (4) at depth k+1
        #pragma unroll
        for (int r = 0; r < 8; r++) {
            float2 sv = *(const float2*)&Ssh[(srow + r) * DD + k];  // broadcast LDS.64
            uint64_t s0 = bcast2(sv.x);
            uint64_t s1 = bcast2(sv.y);
            acc[r][0] = fma2(s0, wa.x, acc[r][0]);
            acc[r][1] = fma2(s0, wa.y, acc[r][1]);
            acc[r][0] = fma2(s1, wb.x, acc[r][0]);
            acc[r][1] = fma2(s1, wb.y, acc[r][1]);
        }
    }

    const float4* hp4 = (const float4*)hprev;
    const float4* b4 = (const float4*)bias;
    #pragma unroll
    for (int r = 0; r < 8; r++) {
        int row = base + srow + r;
        if (row < NN) {
            float2 a01 = unpack2(acc[r][0]);
            float2 a23 = unpack2(acc[r][1]);
            float4 s4 = Ssh4[(srow + r) * 32 + lane];
            float4 o;
            o.x = c0 * a01.x + c1 * s4.x;
            o.y = c0 * a01.y + c1 * s4.y;
            o.z = c0 * a23.x + c1 * s4.z;
            o.w = c0 * a23.y + c1 * s4.w;
            if (hprev) {
                float4 h = hp4[row * 32 + lane];
                o.x += h.x; o.y += h.y; o.z += h.z; o.w += h.w;
            }
            if (bias) {
                float4 b = b4[lane];
                o.x += b.x; o.y += b.y; o.z += b.z; o.w += b.w;
            }
            o.x = fmaxf(o.x, 0.f); o.y = fmaxf(o.y, 0.f);
            o.z = fmaxf(o.z, 0.f); o.w = fmaxf(o.w, 0.f);
            ((float4*)out)[row * 32 + lane] = o;
        }
    }
}

// ---------------- output head: logits = h@w_out + b_out -> log_softmax ----------------
__global__ void k_out(const float* __restrict__ hin, const float* __restrict__ wout,
                      const float* __restrict__ bout, float* __restrict__ out)
{
    __shared__ float Wsh[DD * CC];   // 32KB
    __shared__ float Hsh[8][DD];     // 4KB
    int t = threadIdx.x;

    float4* Wsh4 = (float4*)Wsh;
    const float4* w4 = (const float4*)wout;
    #pragma unroll
    for (int i = 0; i < 8; i++) Wsh4[t + i * 256] = w4[t + i * 256];
    __syncthreads();

    int warp = t >> 5, lane = t & 31;
    int row = blockIdx.x * 8 + warp;
    if (row >= NN) return;

    ((float4*)Hsh[warp])[lane] = ((const float4*)hin)[row * 32 + lane];
    __syncwarp();

    uint64_t accp = *(const uint64_t*)&bout[2 * lane];   // (b0, b1), 8B aligned
    const uint64_t* Wshp = (const uint64_t*)Wsh;         // pair (2*lane, 2*lane+1) per k
    #pragma unroll 4
    for (int k = 0; k < DD; k++) {
        float hv = Hsh[warp][k];
        accp = fma2(bcast2(hv), Wshp[k * 32 + lane], accp);
    }
    float2 a = unpack2(accp);
    float a0 = a.x, a1 = a.y;

    float m = fmaxf(a0, a1);
    #pragma unroll
    for (int off = 16; off; off >>= 1) m = fmaxf(m, __shfl_xor_sync(0xffffffffu, m, off));
    float se = expf(a0 - m) + expf(a1 - m);
    #pragma unroll
    for (int off = 16; off; off >>= 1) se += __shfl_xor_sync(0xffffffffu, se, off);
    float lse = m + logf(se);

    out[row * 64 + 2 * lane]     = a0 - lse;
    out[row * 64 + 2 * lane + 1] = a1 - lse;
}

// ---------------- launch ----------------
extern "C" void kernel_launch(void* const* d_in, const int* in_sizes, int n_in,
                              void* d_out, int out_size)
{
    const float* x     = (const float*)d_in[0];
    const int*   esrc  = (const int*)  d_in[1];
    const int*   edst  = (const int*)  d_in[2];
    const float* ew    = (const float*)d_in[3];
    const float* w_in  = (const float*)d_in[4];
    const float* b_in  = (const float*)d_in[5];
    const float* gcn_w = (const float*)d_in[6];
    const float* w_out = (const float*)d_in[7];
    const float* b_out = (const float*)d_in[8];
    float* out = (float*)d_out;

    const int GEMM_SMEM = (DD * DD + 64 * DD) * (int)sizeof(float); // 98304
    cudaFuncSetAttribute(k_gemm, cudaFuncAttributeMaxDynamicSharedMemorySize, GEMM_SMEM);

    void *ph0v, *phAv, *phBv, *psupv;
    cudaGetSymbolAddress(&ph0v, g_h0);
    cudaGetSymbolAddress(&phAv, g_hA);
    cudaGetSymbolAddress(&phBv, g_hB);
    cudaGetSymbolAddress(&psupv, g_sup);
    float* ph0 = (float*)ph0v;
    float* phA = (float*)phAv;
    float* phB = (float*)phBv;
    float* psup = (float*)psupv;

    const int NB = (NN + 1 + 1023) / 1024; // 98

    // CSR build
    k_zero_rowptr<<<(NN + 1 + 255) / 256, 256>>>();
    k_hist<<<(NE + 255) / 256, 256>>>(edst);
    k_scan1<<<NB, 1024>>>();
    k_scan2<<<1, 128>>>(NB);
    k_scan3<<<NB, 1024>>>();
    k_fill<<<(NE + 255) / 256, 256>>>(esrc, edst, ew);

    const int GB = (NN + 63) / 64;   // 1563 GEMM blocks
    const int SB = NN / 8;           // 12500 warp-per-row blocks

    // h0 = relu(x @ w_in + b_in)
    k_gemm<<<GB, 256, GEMM_SMEM>>>(x, w_in, nullptr, b_in, ph0, 1.0f, 0.0f);

    float theta[NL];
    for (int l = 0; l < NL; l++) theta[l] = logf(0.5f / (float)(l + 2) + 1.0f);

    for (int l = 0; l < NL; l++) {
        float* hin  = (l == 0) ? ph0 : ((l & 1) ? phA : phB);
        float* hout = (l & 1) ? phB : phA;
        k_spmm<<<SB, 256>>>(hin);                       // g_sup = 0.9*A@hin + 0.1*h0
        k_gemm<<<GB, 256, GEMM_SMEM>>>(psup, gcn_w + l * DD * DD, hin, nullptr,
                                       hout, theta[l], 1.0f - theta[l]);
    }

    // final h in g_hB (l=3 -> hout=phB)
    k_out<<<SB, 256>>>(phB, w_out, b_out, out);
}